// round 7
// baseline (speedup 1.0000x reference)
#include <cuda_runtime.h>
#include <cuda_bf16.h>
#include <math.h>
#include <stdint.h>

typedef __nv_bfloat16 bf16;

// ---------------------------------------------------------------------------
// Problem constants
// ---------------------------------------------------------------------------
#define BB 4
#define LL 1024
#define DD 1024
#define HH 16
#define HD 64
#define II 3280
#define I2 6560                // 2*II (fused w1||w3 output cols)
#define I2P 6656               // I2 padded to 128
#define IKP 3328               // II padded to 128 (w2 K)
#define QKVD 3072              // fused qkv row width
#define NROWS (BB * LL)        // 4096
#define EPSV 1e-5f

#define SZ_D ((size_t)NROWS * DD)
#define SZ_I ((size_t)NROWS * II)

// fp32 scratch: qkv(3*SZ_D), a, h, f, z13(2*SZ_I)
__device__ float g_scratch[6 * SZ_D + 2 * SZ_I];
__device__ float g_bias_qkv[QKVD];
__device__ float g_bias_ffn[I2];

// bf16 scratch (hi/lo pairs)
#define BSZ_ACT ((size_t)NROWS * DD)
#define BSZ_G   ((size_t)NROWS * IKP)
#define BSZ_W   ((size_t)I2P * 1024)
__device__ bf16 g_bscratch[6 * BSZ_ACT + 2 * BSZ_G + 2 * BSZ_W];

// ---------------------------------------------------------------------------
// helpers
// ---------------------------------------------------------------------------
__device__ __forceinline__ void split_f32(float v, bf16& hi, bf16& lo) {
    hi = __float2bfloat16(v);
    lo = __float2bfloat16(v - __bfloat162float(hi));
}

__device__ __forceinline__ void cpa16(uint32_t dst_smem, const bf16* src) {
    asm volatile("cp.async.ca.shared.global [%0], [%1], 16;\n"
                 :: "r"(dst_smem), "l"(src));
}
__device__ __forceinline__ void cpa_commit() {
    asm volatile("cp.async.commit_group;\n" ::: "memory");
}
__device__ __forceinline__ void cpa_wait_all() {
    asm volatile("cp.async.wait_group 0;\n" ::: "memory");
}

__device__ __forceinline__ void ldm4(uint32_t* r, uint32_t addr) {
    asm volatile("ldmatrix.sync.aligned.m8n8.x4.shared.b16 {%0,%1,%2,%3}, [%4];\n"
                 : "=r"(r[0]), "=r"(r[1]), "=r"(r[2]), "=r"(r[3]) : "r"(addr));
}

__device__ __forceinline__ void mma16816(float* d, const uint32_t* a, const uint32_t* b) {
    asm volatile(
        "mma.sync.aligned.m16n8k16.row.col.f32.bf16.bf16.f32 "
        "{%0,%1,%2,%3}, {%4,%5,%6,%7}, {%8,%9}, {%0,%1,%2,%3};\n"
        : "+f"(d[0]), "+f"(d[1]), "+f"(d[2]), "+f"(d[3])
        : "r"(a[0]), "r"(a[1]), "r"(a[2]), "r"(a[3]), "r"(b[0]), "r"(b[1]));
}

// ---------------------------------------------------------------------------
// RMSNorm (fp32 out, optional residual)
// ---------------------------------------------------------------------------
template <int W, int T>
__global__ void rmsnorm_k(const float* __restrict__ in,
                          const float* __restrict__ w,
                          const float* __restrict__ resid,
                          float* __restrict__ out)
{
    constexpr int PER = W / T;
    const size_t row = blockIdx.x;
    const float* xr = in + row * (size_t)W;
    float vals[PER];
    float ss = 0.f;
#pragma unroll
    for (int i = 0; i < PER; i++) {
        float vv = xr[threadIdx.x + i * T];
        vv = fminf(fmaxf(vv, -10000.f), 10000.f);
        vals[i] = vv;
        ss += vv * vv;
    }
    __shared__ float red[T];
    red[threadIdx.x] = ss;
    __syncthreads();
#pragma unroll
    for (int s = T / 2; s > 0; s >>= 1) {
        if (threadIdx.x < s) red[threadIdx.x] += red[threadIdx.x + s];
        __syncthreads();
    }
    const float mean = red[0] / (float)W;
    const float inv = 1.f / sqrtf(fmaxf(mean, EPSV) + EPSV);
#pragma unroll
    for (int i = 0; i < PER; i++) {
        const int c = threadIdx.x + i * T;
        float o = vals[i] * inv * w[c];
        if (!isfinite(o)) o = 0.f;
        if (resid) o += resid[row * (size_t)W + c];
        out[row * (size_t)W + c] = o;
    }
}

// RMSNorm writing bf16 hi/lo split
template <int W, int T>
__global__ void rmsnorm_split_k(const float* __restrict__ in,
                                const float* __restrict__ w,
                                bf16* __restrict__ ohi,
                                bf16* __restrict__ olo)
{
    constexpr int PER = W / T;
    const size_t row = blockIdx.x;
    const float* xr = in + row * (size_t)W;
    float vals[PER];
    float ss = 0.f;
#pragma unroll
    for (int i = 0; i < PER; i++) {
        float vv = xr[threadIdx.x + i * T];
        vv = fminf(fmaxf(vv, -10000.f), 10000.f);
        vals[i] = vv;
        ss += vv * vv;
    }
    __shared__ float red[T];
    red[threadIdx.x] = ss;
    __syncthreads();
#pragma unroll
    for (int s = T / 2; s > 0; s >>= 1) {
        if (threadIdx.x < s) red[threadIdx.x] += red[threadIdx.x + s];
        __syncthreads();
    }
    const float mean = red[0] / (float)W;
    const float inv = 1.f / sqrtf(fmaxf(mean, EPSV) + EPSV);
#pragma unroll
    for (int i = 0; i < PER; i++) {
        const int c = threadIdx.x + i * T;
        float o = vals[i] * inv * w[c];
        if (!isfinite(o)) o = 0.f;
        bf16 hi, lo;
        split_f32(o, hi, lo);
        ohi[row * (size_t)W + c] = hi;
        olo[row * (size_t)W + c] = lo;
    }
}

// per-head rmsnorm (in-place on strided qkv buffer; 64 threads)
__global__ void rmsnorm_head_k(float* __restrict__ qkv,
                               const float* __restrict__ w, int colOff)
{
    const int ri = blockIdx.x;
    const int r = ri >> 4;
    const int h = ri & 15;
    float* xr = qkv + (size_t)r * QKVD + colOff + h * HD;
    const int t = threadIdx.x;
    float vv = xr[t];
    vv = fminf(fmaxf(vv, -10000.f), 10000.f);
    __shared__ float red[64];
    red[t] = vv * vv;
    __syncthreads();
#pragma unroll
    for (int s = 32; s > 0; s >>= 1) {
        if (t < s) red[t] += red[t + s];
        __syncthreads();
    }
    const float mean = red[0] / 64.f;
    const float inv = 1.f / sqrtf(fmaxf(mean, EPSV) + EPSV);
    float o = vv * inv * w[t];
    if (!isfinite(o)) o = 0.f;
    xr[t] = o;
}

// ---------------------------------------------------------------------------
// Weight split with row+col padding
// ---------------------------------------------------------------------------
__global__ void conv_split_k(const float* __restrict__ src,
                             bf16* __restrict__ hi, bf16* __restrict__ lo,
                             int rows, int K0, int rowsPad, int KP)
{
    size_t idx = (size_t)blockIdx.x * blockDim.x + threadIdx.x;
    size_t n = (size_t)rowsPad * KP;
    if (idx >= n) return;
    int r = (int)(idx / KP);
    int c = (int)(idx % KP);
    float v = (r < rows && c < K0) ? src[(size_t)r * K0 + c] : 0.f;
    bf16 h, l;
    split_f32(v, h, l);
    hi[idx] = h;
    lo[idx] = l;
}

// bias concat for fused GEMMs
__global__ void bias_concat_k(const float* qb, const float* kb, const float* vb,
                              const float* b1, const float* b3,
                              float* outQKV, float* outFFN)
{
    int i = blockIdx.x * blockDim.x + threadIdx.x;
    if (i < 1024) {
        outQKV[i] = qb[i];
        outQKV[1024 + i] = kb[i];
        outQKV[2048 + i] = vb[i];
    }
    if (i < II) {
        outFFN[i] = b1[i];
        outFFN[II + i] = b3[i];
    }
}

// ---------------------------------------------------------------------------
// silu(z1)*z3 from fused z13[4096][I2] -> bf16 hi/lo at stride IKP
// ---------------------------------------------------------------------------
__global__ void silu_split_k(const float* __restrict__ z13,
                             bf16* __restrict__ ghi, bf16* __restrict__ glo)
{
    size_t idx = (size_t)blockIdx.x * blockDim.x + threadIdx.x;
    size_t n = (size_t)NROWS * IKP;
    if (idx >= n) return;
    int r = (int)(idx / IKP);
    int c = (int)(idx % IKP);
    float g = 0.f;
    if (c < II) {
        float a = z13[(size_t)r * I2 + c];
        float z3v = z13[(size_t)r * I2 + II + c];
        float sv = a / (1.f + expf(-a));
        g = sv * z3v;
    }
    bf16 h, l;
    split_f32(g, h, l);
    ghi[idx] = h;
    glo[idx] = l;
}

// ---------------------------------------------------------------------------
// bf16x3 tensor-core GEMM (NT): C[n,m] = sum_k A[n,k]*B[m,k] + bias[m]
// CTA 128x128, BK=32, 128 threads (4 warps of 64x64).
// cp.async double-buffered, pad-40 rows, ldmatrix fragments, mma.sync bf16.
// K multiple of 32; B row-padded to multiples of 128; N rows multiple of 128.
// ---------------------------------------------------------------------------
#define SKT 40
#define TILE_BYTES (128 * SKT * 2)      // 10240 per array
#define STAGE_BYTES (4 * TILE_BYTES)    // 40960
#define GEMM_SMEM (2 * STAGE_BYTES)     // 81920

__global__ void __launch_bounds__(128, 2)
gemm_bf16x3(const bf16* __restrict__ Ah, const bf16* __restrict__ Al,
            const bf16* __restrict__ Bh, const bf16* __restrict__ Bl,
            const float* __restrict__ bias, float* __restrict__ C,
            int Mtot, int K, int ldc)
{
    extern __shared__ __align__(16) bf16 smem[];
    const uint32_t sb = (uint32_t)__cvta_generic_to_shared(smem);

    const int tid = threadIdx.x;
    const int lane = tid & 31;
    const int wid = tid >> 5;
    const int wr = wid >> 1;   // 0..1 (M half)
    const int wc = wid & 1;    // 0..1 (N half)

    const int bm = blockIdx.x * 128;
    const int bn = blockIdx.y * 128;

    const bf16* gAh = Ah + (size_t)(bn + tid) * K;
    const bf16* gAl = Al + (size_t)(bn + tid) * K;
    const bf16* gBh = Bh + (size_t)(bm + tid) * K;
    const bf16* gBl = Bl + (size_t)(bm + tid) * K;
    const uint32_t srow = (uint32_t)(tid * SKT) * 2;   // byte offset of my row

    float acc[4][8][4];
#pragma unroll
    for (int i = 0; i < 4; i++)
#pragma unroll
        for (int j = 0; j < 8; j++)
#pragma unroll
            for (int r = 0; r < 4; r++) acc[i][j][r] = 0.f;

    const int nk = K >> 5;

    // prologue: stage 0
#pragma unroll
    for (int c = 0; c < 4; c++) {
        const uint32_t doff = srow + c * 16;
        cpa16(sb + 0 * TILE_BYTES + doff, gAh + c * 8);
        cpa16(sb + 1 * TILE_BYTES + doff, gAl + c * 8);
        cpa16(sb + 2 * TILE_BYTES + doff, gBh + c * 8);
        cpa16(sb + 3 * TILE_BYTES + doff, gBl + c * 8);
    }
    cpa_commit();

    // fragment address components
    const int a_row = wr * 64 + (lane & 15);
    const int a_ksel = ((lane >> 4) & 1) * 8;
    const int b_row = wc * 64 + ((lane >> 4) & 1) * 8 + (lane & 7);
    const int b_ksel = ((lane >> 3) & 1) * 8;

    for (int kt = 0; kt < nk; kt++) {
        cpa_wait_all();
        __syncthreads();

        if (kt + 1 < nk) {
            const uint32_t st = sb + ((kt + 1) & 1) * STAGE_BYTES;
            const int ko = (kt + 1) << 5;
#pragma unroll
            for (int c = 0; c < 4; c++) {
                const uint32_t doff = srow + c * 16;
                cpa16(st + 0 * TILE_BYTES + doff, gAh + ko + c * 8);
                cpa16(st + 1 * TILE_BYTES + doff, gAl + ko + c * 8);
                cpa16(st + 2 * TILE_BYTES + doff, gBh + ko + c * 8);
                cpa16(st + 3 * TILE_BYTES + doff, gBl + ko + c * 8);
            }
        }
        cpa_commit();

        const uint32_t st = sb + (kt & 1) * STAGE_BYTES;
#pragma unroll
        for (int ks = 0; ks < 2; ks++) {
            uint32_t ah[4][4], al[4][4], bh[8][2], bl[8][2];
#pragma unroll
            for (int mi = 0; mi < 4; mi++) {
                const uint32_t off =
                    (uint32_t)((a_row + mi * 16) * SKT + ks * 16 + a_ksel) * 2;
                ldm4(ah[mi], st + 0 * TILE_BYTES + off);
                ldm4(al[mi], st + 1 * TILE_BYTES + off);
            }
#pragma unroll
            for (int p = 0; p < 4; p++) {
                const uint32_t off =
                    (uint32_t)((b_row + p * 16) * SKT + ks * 16 + b_ksel) * 2;
                uint32_t th[4], tl[4];
                ldm4(th, st + 2 * TILE_BYTES + off);
                ldm4(tl, st + 3 * TILE_BYTES + off);
                bh[p * 2][0] = th[0]; bh[p * 2][1] = th[1];
                bh[p * 2 + 1][0] = th[2]; bh[p * 2 + 1][1] = th[3];
                bl[p * 2][0] = tl[0]; bl[p * 2][1] = tl[1];
                bl[p * 2 + 1][0] = tl[2]; bl[p * 2 + 1][1] = tl[3];
            }
#pragma unroll
            for (int mi = 0; mi < 4; mi++)
#pragma unroll
                for (int ni = 0; ni < 8; ni++) {
                    mma16816(acc[mi][ni], ah[mi], bh[ni]);
                    mma16816(acc[mi][ni], ah[mi], bl[ni]);
                    mma16816(acc[mi][ni], al[mi], bh[ni]);
                }
        }
        __syncthreads();
    }

    // epilogue
    const int trow = lane >> 2;
    const int tcol = (lane & 3) * 2;
#pragma unroll
    for (int mi = 0; mi < 4; mi++) {
        const size_t r1 = (size_t)bn + wr * 64 + mi * 16 + trow;
        const size_t r2 = r1 + 8;
#pragma unroll
        for (int ni = 0; ni < 8; ni++) {
            const int col = bm + wc * 64 + ni * 8 + tcol;
            if (col < Mtot) {
                const float b0 = bias[col];
                const float b1 = bias[col + 1];
                float2 v0 = make_float2(acc[mi][ni][0] + b0, acc[mi][ni][1] + b1);
                float2 v1 = make_float2(acc[mi][ni][2] + b0, acc[mi][ni][3] + b1);
                *(float2*)&C[r1 * (size_t)ldc + col] = v0;
                *(float2*)&C[r2 * (size_t)ldc + col] = v1;
            }
        }
    }
}

// ---------------------------------------------------------------------------
// Tiled sliding-window attention (flash style), strided q/k/v (fused qkv),
// writes bf16 hi/lo split at stride DD.
// ---------------------------------------------------------------------------
#define ATT_SMEM_FLOATS (4 * 64 * 64 + 3 * 64)

__global__ void __launch_bounds__(256)
attn_tile_kernel(const float* __restrict__ q, const float* __restrict__ k,
                 const float* __restrict__ v,
                 bf16* __restrict__ ohi, bf16* __restrict__ olo,
                 const int* __restrict__ winp, int qs)
{
    extern __shared__ float sm[];
    float* Qs  = sm;
    float* Kst = Qs + 64 * 64;
    float* Vs  = Kst + 64 * 64;
    float* Ss  = Vs + 64 * 64;
    float* m_s = Ss + 64 * 64;
    float* l_s = m_s + 64;
    float* sc_s = l_s + 64;

    const int q0 = blockIdx.x * 64;
    const int h  = blockIdx.y;
    const int b  = blockIdx.z;
    const int tid = threadIdx.x;
    const int win = *winp;

    const size_t base_q = ((size_t)(b * LL + q0)) * qs + h * HD;

    for (int i = tid; i < 1024; i += 256) {
        const int r = i >> 4;
        const int d4 = (i & 15) << 2;
        *(float4*)&Qs[r * 64 + d4] =
            *(const float4*)&q[base_q + (size_t)r * qs + d4];
    }
    if (tid < 64) { m_s[tid] = -INFINITY; l_s[tid] = 0.f; }

    const int ty = tid >> 4;
    const int tx = tid & 15;
    float accO[4][4];
#pragma unroll
    for (int i = 0; i < 4; i++)
#pragma unroll
        for (int j = 0; j < 4; j++) accO[i][j] = 0.f;

    int lo = q0 - win + 1;
    if (lo < 0) lo = 0;
    const int kt0 = lo >> 6;
    const int kt1 = q0 >> 6;

    __syncthreads();

    for (int kt = kt0; kt <= kt1; kt++) {
        const int j0 = kt << 6;
        const size_t base_k = ((size_t)(b * LL + j0)) * qs + h * HD;

        for (int i = tid; i < 1024; i += 256) {
            const int r = i >> 4;
            const int d4 = (i & 15) << 2;
            const float4 kv = *(const float4*)&k[base_k + (size_t)r * qs + d4];
            Kst[(d4 + 0) * 64 + r] = kv.x;
            Kst[(d4 + 1) * 64 + r] = kv.y;
            Kst[(d4 + 2) * 64 + r] = kv.z;
            Kst[(d4 + 3) * 64 + r] = kv.w;
            *(float4*)&Vs[r * 64 + d4] =
                *(const float4*)&v[base_k + (size_t)r * qs + d4];
        }
        __syncthreads();

        float accS[4][4];
#pragma unroll
        for (int i = 0; i < 4; i++)
#pragma unroll
            for (int j = 0; j < 4; j++) accS[i][j] = 0.f;

        for (int d = 0; d < 64; d += 4) {
            float4 qv[4];
#pragma unroll
            for (int i = 0; i < 4; i++)
                qv[i] = *(const float4*)&Qs[(ty * 4 + i) * 64 + d];
#pragma unroll
            for (int dd = 0; dd < 4; dd++) {
                const float4 kv = *(const float4*)&Kst[(d + dd) * 64 + tx * 4];
#pragma unroll
                for (int i = 0; i < 4; i++) {
                    const float qq = ((const float*)&qv[i])[dd];
                    accS[i][0] = fmaf(qq, kv.x, accS[i][0]);
                    accS[i][1] = fmaf(qq, kv.y, accS[i][1]);
                    accS[i][2] = fmaf(qq, kv.z, accS[i][2]);
                    accS[i][3] = fmaf(qq, kv.w, accS[i][3]);
                }
            }
        }

#pragma unroll
        for (int i = 0; i < 4; i++) {
            const int qi = q0 + ty * 4 + i;
#pragma unroll
            for (int j = 0; j < 4; j++) {
                const int jj = j0 + tx * 4 + j;
                const bool ok = (jj <= qi) && (qi - jj < win);
                Ss[(ty * 4 + i) * 64 + tx * 4 + j] =
                    ok ? accS[i][j] * 0.125f : -INFINITY;
            }
        }
        __syncthreads();

        {
            const int row = tid >> 2;
            const int part = tid & 3;
            float* srow = &Ss[row * 64 + part * 16];
            float tm = -INFINITY;
#pragma unroll
            for (int c = 0; c < 16; c++) tm = fmaxf(tm, srow[c]);
            tm = fmaxf(tm, __shfl_xor_sync(0xffffffffu, tm, 1));
            tm = fmaxf(tm, __shfl_xor_sync(0xffffffffu, tm, 2));

            const float mold = m_s[row];
            const float nm = fmaxf(mold, tm);
            float scale;
            float psum = 0.f;
            if (nm == -INFINITY) {
                scale = 1.f;
#pragma unroll
                for (int c = 0; c < 16; c++) srow[c] = 0.f;
            } else {
                scale = expf(mold - nm);
#pragma unroll
                for (int c = 0; c < 16; c++) {
                    const float p = expf(srow[c] - nm);
                    srow[c] = p;
                    psum += p;
                }
            }
            psum += __shfl_xor_sync(0xffffffffu, psum, 1);
            psum += __shfl_xor_sync(0xffffffffu, psum, 2);
            if (part == 0) {
                m_s[row] = nm;
                l_s[row] = l_s[row] * scale + psum;
                sc_s[row] = scale;
            }
        }
        __syncthreads();

#pragma unroll
        for (int i = 0; i < 4; i++) {
            const float s = sc_s[ty * 4 + i];
#pragma unroll
            for (int j = 0; j < 4; j++) accO[i][j] *= s;
        }
        for (int kk = 0; kk < 64; kk += 4) {
            float4 pv[4];
#pragma unroll
            for (int i = 0; i < 4; i++)
                pv[i] = *(const float4*)&Ss[(ty * 4 + i) * 64 + kk];
#pragma unroll
            for (int dd = 0; dd < 4; dd++) {
                const float4 vv = *(const float4*)&Vs[(kk + dd) * 64 + tx * 4];
#pragma unroll
                for (int i = 0; i < 4; i++) {
                    const float pp = ((const float*)&pv[i])[dd];
                    accO[i][0] = fmaf(pp, vv.x, accO[i][0]);
                    accO[i][1] = fmaf(pp, vv.y, accO[i][1]);
                    accO[i][2] = fmaf(pp, vv.z, accO[i][2]);
                    accO[i][3] = fmaf(pp, vv.w, accO[i][3]);
                }
            }
        }
        __syncthreads();
    }

#pragma unroll
    for (int i = 0; i < 4; i++) {
        const int r = ty * 4 + i;
        const float linv = 1.f / l_s[r];
#pragma unroll
        for (int j = 0; j < 4; j++) {
            float outv = accO[i][j] * linv;
            if (!isfinite(outv)) outv = 0.f;
            bf16 hi, lo2;
            split_f32(outv, hi, lo2);
            const size_t idx = ((size_t)(b * LL + q0 + r)) * DD + h * HD + tx * 4 + j;
            ohi[idx] = hi;
            olo[idx] = lo2;
        }
    }
}

// ---------------------------------------------------------------------------
// Launch
// ---------------------------------------------------------------------------
extern "C" void kernel_launch(void* const* d_in, const int* in_sizes, int n_in,
                              void* d_out, int out_size)
{
    const float* x    = (const float*)d_in[0];
    const float* wq_w = (const float*)d_in[1];
    const float* wq_b = (const float*)d_in[2];
    const float* wk_w = (const float*)d_in[3];
    const float* wk_b = (const float*)d_in[4];
    const float* wv_w = (const float*)d_in[5];
    const float* wv_b = (const float*)d_in[6];
    const float* wo_w = (const float*)d_in[7];
    const float* wo_b = (const float*)d_in[8];
    const float* q_nw = (const float*)d_in[9];
    const float* k_nw = (const float*)d_in[10];
    const float* s_nw = (const float*)d_in[11];
    const float* sp_nw= (const float*)d_in[12];
    const float* f_nw = (const float*)d_in[13];
    const float* fp_nw= (const float*)d_in[14];
    const float* w1_w = (const float*)d_in[15];
    const float* w1_b = (const float*)d_in[16];
    const float* w2_w = (const float*)d_in[17];
    const float* w2_b = (const float*)d_in[18];
    const float* w3_w = (const float*)d_in[19];
    const float* w3_b = (const float*)d_in[20];
    const int*   winp = (const int*)d_in[21];

    float* fbase = nullptr;
    cudaGetSymbolAddress((void**)&fbase, g_scratch);
    float* qkv = fbase;                       // [4096][3072]
    float* a   = fbase + 3 * SZ_D;
    float* h   = fbase + 4 * SZ_D;
    float* f   = fbase + 5 * SZ_D;
    float* z13 = fbase + 6 * SZ_D;            // [4096][6560]

    float* bqkv = nullptr;
    cudaGetSymbolAddress((void**)&bqkv, g_bias_qkv);
    float* bffn = nullptr;
    cudaGetSymbolAddress((void**)&bffn, g_bias_ffn);

    bf16* bbase = nullptr;
    cudaGetSymbolAddress((void**)&bbase, g_bscratch);
    bf16* xn_h = bbase + 0 * BSZ_ACT;
    bf16* xn_l = bbase + 1 * BSZ_ACT;
    bf16* at_h = bbase + 2 * BSZ_ACT;
    bf16* at_l = bbase + 3 * BSZ_ACT;
    bf16* hn_h = bbase + 4 * BSZ_ACT;
    bf16* hn_l = bbase + 5 * BSZ_ACT;
    bf16* g_h  = bbase + 6 * BSZ_ACT;
    bf16* g_l  = bbase + 6 * BSZ_ACT + BSZ_G;
    bf16* w_h  = bbase + 6 * BSZ_ACT + 2 * BSZ_G;
    bf16* w_l  = bbase + 6 * BSZ_ACT + 2 * BSZ_G + BSZ_W;

    float* out = (float*)d_out;

    cudaFuncSetAttribute(gemm_bf16x3,
                         cudaFuncAttributeMaxDynamicSharedMemorySize, GEMM_SMEM);

    // biases for fused GEMMs
    bias_concat_k<<<(II + 255) / 256, 256>>>(wq_b, wk_b, wv_b, w1_b, w3_b,
                                             bqkv, bffn);

    // 1) xn = rmsnorm(x, seq_norm_w) -> bf16 split
    rmsnorm_split_k<DD, 256><<<NROWS, 256>>>(x, s_nw, xn_h, xn_l);

    // 2) fused QKV projection
    {
        const int wN = DD * DD;
        conv_split_k<<<(wN + 255) / 256, 256>>>(wq_w, w_h, w_l, DD, DD, DD, DD);
        conv_split_k<<<(wN + 255) / 256, 256>>>(wk_w, w_h + (size_t)1024 * 1024,
                                                w_l + (size_t)1024 * 1024, DD, DD, DD, DD);
        conv_split_k<<<(wN + 255) / 256, 256>>>(wv_w, w_h + (size_t)2048 * 1024,
                                                w_l + (size_t)2048 * 1024, DD, DD, DD, DD);
        dim3 grid(QKVD / 128, NROWS / 128);
        gemm_bf16x3<<<grid, 128, GEMM_SMEM>>>(xn_h, xn_l, w_h, w_l, bqkv, qkv,
                                              QKVD, DD, QKVD);
    }

    // 3) per-head q/k rmsnorm (in-place on qkv)
    rmsnorm_head_k<<<NROWS * HH, 64>>>(qkv, q_nw, 0);
    rmsnorm_head_k<<<NROWS * HH, 64>>>(qkv, k_nw, 1024);

    // 4) attention -> bf16 split output
    {
        const size_t smem_bytes = (size_t)ATT_SMEM_FLOATS * sizeof(float);
        cudaFuncSetAttribute(attn_tile_kernel,
                             cudaFuncAttributeMaxDynamicSharedMemorySize,
                             (int)smem_bytes);
        dim3 grid(LL / 64, HH, BB);
        attn_tile_kernel<<<grid, 256, smem_bytes>>>(qkv, qkv + 1024, qkv + 2048,
                                                    at_h, at_l, winp, QKVD);
    }

    // 5) output projection
    {
        const int wN = DD * DD;
        conv_split_k<<<(wN + 255) / 256, 256>>>(wo_w, w_h, w_l, DD, DD, DD, DD);
        dim3 grid(DD / 128, NROWS / 128);
        gemm_bf16x3<<<grid, 128, GEMM_SMEM>>>(at_h, at_l, w_h, w_l, wo_b, a,
                                              DD, DD, DD);
    }

    // 6) h = x + rmsnorm(a, seq_post_norm_w)
    rmsnorm_k<DD, 256><<<NROWS, 256>>>(a, sp_nw, x, h);

    // 7) hn = rmsnorm(h, ffn_norm_w) -> bf16 split
    rmsnorm_split_k<DD, 256><<<NROWS, 256>>>(h, f_nw, hn_h, hn_l);

    // 8) fused w1||w3 GEMM -> z13
    {
        const size_t wN1 = (size_t)II * DD;
        conv_split_k<<<(int)((wN1 + 255) / 256), 256>>>(w1_w, w_h, w_l,
                                                        II, DD, II, DD);
        const size_t off = (size_t)II * DD;
        const size_t wN2 = (size_t)(I2P - II) * DD;   // rows 3280..6655 (pad tail)
        conv_split_k<<<(int)((wN2 + 255) / 256), 256>>>(w3_w, w_h + off, w_l + off,
                                                        II, DD, I2P - II, DD);
        dim3 grid(I2P / 128, NROWS / 128);
        gemm_bf16x3<<<grid, 128, GEMM_SMEM>>>(hn_h, hn_l, w_h, w_l, bffn, z13,
                                              I2, DD, I2);
    }

    // 9) g = silu(z1)*z3 -> bf16 split (stride IKP, zero pad)
    {
        size_t n = (size_t)NROWS * IKP;
        silu_split_k<<<(int)((n + 255) / 256), 256>>>(z13, g_h, g_l);
    }

    // 10) f = g @ w2^T + b2  (K = IKP, weight K-padded)
    {
        const size_t wN = (size_t)DD * IKP;
        conv_split_k<<<(int)((wN + 255) / 256), 256>>>(w2_w, w_h, w_l,
                                                       DD, II, DD, IKP);
        dim3 grid(DD / 128, NROWS / 128);
        gemm_bf16x3<<<grid, 128, GEMM_SMEM>>>(g_h, g_l, w_h, w_l, w2_b, f,
                                              DD, IKP, DD);
    }

    // 11) out = h + rmsnorm(f, ffn_post_norm_w)
    rmsnorm_k<DD, 256><<<NROWS, 256>>>(f, fp_nw, h, out);
}

// round 8
// speedup vs baseline: 1.4372x; 1.4372x over previous
#include <cuda_runtime.h>
#include <cuda_bf16.h>
#include <math.h>
#include <stdint.h>

typedef __nv_bfloat16 bf16;

// ---------------------------------------------------------------------------
// Problem constants
// ---------------------------------------------------------------------------
#define BB 4
#define LL 1024
#define DD 1024
#define HH 16
#define HD 64
#define II 3280
#define I2 6560                // 2*II (fused w1||w3 output cols)
#define I2P 6656               // I2 padded to 128
#define IKP 3328               // II padded to 128 (w2 K)
#define QKVD 3072              // fused qkv row width
#define NROWS (BB * LL)        // 4096
#define EPSV 1e-5f

#define SZ_D ((size_t)NROWS * DD)
#define SZ_I ((size_t)NROWS * II)

// fp32 scratch: qkv(3*SZ_D), a, h, f, z13(2*SZ_I)
__device__ float g_scratch[6 * SZ_D + 2 * SZ_I];
__device__ float g_bias_qkv[QKVD];
__device__ float g_bias_ffn[I2];

// bf16 scratch (hi/lo pairs)
#define BSZ_ACT ((size_t)NROWS * DD)
#define BSZ_G   ((size_t)NROWS * IKP)
#define BSZ_W   ((size_t)I2P * 1024)
__device__ bf16 g_bscratch[6 * BSZ_ACT + 2 * BSZ_G + 2 * BSZ_W];

// ---------------------------------------------------------------------------
// helpers
// ---------------------------------------------------------------------------
__device__ __forceinline__ void split_f32(float v, bf16& hi, bf16& lo) {
    hi = __float2bfloat16(v);
    lo = __float2bfloat16(v - __bfloat162float(hi));
}

// cp.async with src-size predicate: sz=0 -> zero-fill
__device__ __forceinline__ void cpa16p(bf16* dst, const bf16* src, bool valid) {
    uint32_t d = (uint32_t)__cvta_generic_to_shared(dst);
    int sz = valid ? 16 : 0;
    asm volatile("cp.async.ca.shared.global [%0], [%1], 16, %2;\n"
                 :: "r"(d), "l"(src), "r"(sz));
}
__device__ __forceinline__ void cpa_commit() {
    asm volatile("cp.async.commit_group;\n" ::: "memory");
}
__device__ __forceinline__ void cpa_wait_all() {
    asm volatile("cp.async.wait_group 0;\n" ::: "memory");
}

__device__ __forceinline__ void ldm4(uint32_t* r, uint32_t addr) {
    asm volatile("ldmatrix.sync.aligned.m8n8.x4.shared.b16 {%0,%1,%2,%3}, [%4];\n"
                 : "=r"(r[0]), "=r"(r[1]), "=r"(r[2]), "=r"(r[3]) : "r"(addr));
}

__device__ __forceinline__ void mma16816(float* d, const uint32_t* a, const uint32_t* b) {
    asm volatile(
        "mma.sync.aligned.m16n8k16.row.col.f32.bf16.bf16.f32 "
        "{%0,%1,%2,%3}, {%4,%5,%6,%7}, {%8,%9}, {%0,%1,%2,%3};\n"
        : "+f"(d[0]), "+f"(d[1]), "+f"(d[2]), "+f"(d[3])
        : "r"(a[0]), "r"(a[1]), "r"(a[2]), "r"(a[3]), "r"(b[0]), "r"(b[1]));
}

// ---------------------------------------------------------------------------
// RMSNorm (fp32 out, optional residual)
// ---------------------------------------------------------------------------
template <int W, int T>
__global__ void rmsnorm_k(const float* __restrict__ in,
                          const float* __restrict__ w,
                          const float* __restrict__ resid,
                          float* __restrict__ out)
{
    constexpr int PER = W / T;
    const size_t row = blockIdx.x;
    const float* xr = in + row * (size_t)W;
    float vals[PER];
    float ss = 0.f;
#pragma unroll
    for (int i = 0; i < PER; i++) {
        float vv = xr[threadIdx.x + i * T];
        vv = fminf(fmaxf(vv, -10000.f), 10000.f);
        vals[i] = vv;
        ss += vv * vv;
    }
    __shared__ float red[T];
    red[threadIdx.x] = ss;
    __syncthreads();
#pragma unroll
    for (int s = T / 2; s > 0; s >>= 1) {
        if (threadIdx.x < s) red[threadIdx.x] += red[threadIdx.x + s];
        __syncthreads();
    }
    const float mean = red[0] / (float)W;
    const float inv = 1.f / sqrtf(fmaxf(mean, EPSV) + EPSV);
#pragma unroll
    for (int i = 0; i < PER; i++) {
        const int c = threadIdx.x + i * T;
        float o = vals[i] * inv * w[c];
        if (!isfinite(o)) o = 0.f;
        if (resid) o += resid[row * (size_t)W + c];
        out[row * (size_t)W + c] = o;
    }
}

// RMSNorm writing bf16 hi/lo split
template <int W, int T>
__global__ void rmsnorm_split_k(const float* __restrict__ in,
                                const float* __restrict__ w,
                                bf16* __restrict__ ohi,
                                bf16* __restrict__ olo)
{
    constexpr int PER = W / T;
    const size_t row = blockIdx.x;
    const float* xr = in + row * (size_t)W;
    float vals[PER];
    float ss = 0.f;
#pragma unroll
    for (int i = 0; i < PER; i++) {
        float vv = xr[threadIdx.x + i * T];
        vv = fminf(fmaxf(vv, -10000.f), 10000.f);
        vals[i] = vv;
        ss += vv * vv;
    }
    __shared__ float red[T];
    red[threadIdx.x] = ss;
    __syncthreads();
#pragma unroll
    for (int s = T / 2; s > 0; s >>= 1) {
        if (threadIdx.x < s) red[threadIdx.x] += red[threadIdx.x + s];
        __syncthreads();
    }
    const float mean = red[0] / (float)W;
    const float inv = 1.f / sqrtf(fmaxf(mean, EPSV) + EPSV);
#pragma unroll
    for (int i = 0; i < PER; i++) {
        const int c = threadIdx.x + i * T;
        float o = vals[i] * inv * w[c];
        if (!isfinite(o)) o = 0.f;
        bf16 hi, lo;
        split_f32(o, hi, lo);
        ohi[row * (size_t)W + c] = hi;
        olo[row * (size_t)W + c] = lo;
    }
}

// per-head rmsnorm (in-place on strided qkv buffer; 64 threads)
__global__ void rmsnorm_head_k(float* __restrict__ qkv,
                               const float* __restrict__ w, int colOff)
{
    const int ri = blockIdx.x;
    const int r = ri >> 4;
    const int h = ri & 15;
    float* xr = qkv + (size_t)r * QKVD + colOff + h * HD;
    const int t = threadIdx.x;
    float vv = xr[t];
    vv = fminf(fmaxf(vv, -10000.f), 10000.f);
    __shared__ float red[64];
    red[t] = vv * vv;
    __syncthreads();
#pragma unroll
    for (int s = 32; s > 0; s >>= 1) {
        if (t < s) red[t] += red[t + s];
        __syncthreads();
    }
    const float mean = red[0] / 64.f;
    const float inv = 1.f / sqrtf(fmaxf(mean, EPSV) + EPSV);
    float o = vv * inv * w[t];
    if (!isfinite(o)) o = 0.f;
    xr[t] = o;
}

// ---------------------------------------------------------------------------
// Weight split with row+col padding
// ---------------------------------------------------------------------------
__global__ void conv_split_k(const float* __restrict__ src,
                             bf16* __restrict__ hi, bf16* __restrict__ lo,
                             int rows, int K0, int rowsPad, int KP)
{
    size_t idx = (size_t)blockIdx.x * blockDim.x + threadIdx.x;
    size_t n = (size_t)rowsPad * KP;
    if (idx >= n) return;
    int r = (int)(idx / KP);
    int c = (int)(idx % KP);
    float v = (r < rows && c < K0) ? src[(size_t)r * K0 + c] : 0.f;
    bf16 h, l;
    split_f32(v, h, l);
    hi[idx] = h;
    lo[idx] = l;
}

// bias concat for fused GEMMs
__global__ void bias_concat_k(const float* qb, const float* kb, const float* vb,
                              const float* b1, const float* b3,
                              float* outQKV, float* outFFN)
{
    int i = blockIdx.x * blockDim.x + threadIdx.x;
    if (i < 1024) {
        outQKV[i] = qb[i];
        outQKV[1024 + i] = kb[i];
        outQKV[2048 + i] = vb[i];
    }
    if (i < II) {
        outFFN[i] = b1[i];
        outFFN[II + i] = b3[i];
    }
}

// ---------------------------------------------------------------------------
// silu(z1)*z3 from fused z13[4096][I2] -> bf16 hi/lo at stride IKP
// ---------------------------------------------------------------------------
__global__ void silu_split_k(const float* __restrict__ z13,
                             bf16* __restrict__ ghi, bf16* __restrict__ glo)
{
    size_t idx = (size_t)blockIdx.x * blockDim.x + threadIdx.x;
    size_t n = (size_t)NROWS * IKP;
    if (idx >= n) return;
    int r = (int)(idx / IKP);
    int c = (int)(idx % IKP);
    float g = 0.f;
    if (c < II) {
        float a = z13[(size_t)r * I2 + c];
        float z3v = z13[(size_t)r * I2 + II + c];
        float sv = a / (1.f + expf(-a));
        g = sv * z3v;
    }
    bf16 h, l;
    split_f32(g, h, l);
    ghi[idx] = h;
    glo[idx] = l;
}

// ---------------------------------------------------------------------------
// bf16x3 tensor-core GEMM (NT): C[n,m] = sum_k A[n,k]*B[m,k] + bias[m]
// Proven R5 config: CTA 128x128, BK=32, 256 threads (8 warps, 2x4; 64x32/warp),
// cp.async double-buffered, pad-40 rows, ldmatrix fragments, mma.sync bf16.
// K multiple of 32; M guarded (src-size-predicated loads + store guards).
// ---------------------------------------------------------------------------
#define SKT 40
#define STAGE_ELEMS (128 * SKT)                    // per array, bf16
#define GEMM_SMEM (2 * 4 * STAGE_ELEMS * 2)        // 81920 bytes

__global__ void __launch_bounds__(256)
gemm_bf16x3(const bf16* __restrict__ Ah, const bf16* __restrict__ Al,
            const bf16* __restrict__ Bh, const bf16* __restrict__ Bl,
            const float* __restrict__ bias, float* __restrict__ C,
            int Mtot, int K, int ldc)
{
    extern __shared__ __align__(16) bf16 smem[];
    // layout: [stage][Ah | Al | Bh | Bl], each STAGE_ELEMS

    const int tid = threadIdx.x;
    const int lane = tid & 31;
    const int wid = tid >> 5;
    const int wm = wid & 1;   // warp row (M of output rows)
    const int wn = wid >> 1;  // warp col

    const int bm = blockIdx.x * 128;  // output col tile (weights dim)
    const int bn = blockIdx.y * 128;  // output row tile

    // global->smem loader mapping: thread t -> row t/2, 16-elem chunk (t&1)
    const int ldr = tid >> 1;
    const int ldcol = (tid & 1) * 16;

    const bf16* gAh = Ah + (size_t)(bn + ldr) * K + ldcol;
    const bf16* gAl = Al + (size_t)(bn + ldr) * K + ldcol;
    const bool bvalid = (bm + ldr) < Mtot;
    const bf16* gBh = Bh + (size_t)(bm + ldr) * K + ldcol;
    const bf16* gBl = Bl + (size_t)(bm + ldr) * K + ldcol;

    const int s_off = ldr * SKT + ldcol;

    float acc[4][4][4];
#pragma unroll
    for (int i = 0; i < 4; i++)
#pragma unroll
        for (int j = 0; j < 4; j++)
#pragma unroll
            for (int r = 0; r < 4; r++) acc[i][j][r] = 0.f;

    const int nk = K >> 5;   // BK=32 tiles

    // prologue: stage 0
    {
        bf16* s = smem;
        cpa16p(s + 0 * STAGE_ELEMS + s_off,     gAh,     true);
        cpa16p(s + 0 * STAGE_ELEMS + s_off + 8, gAh + 8, true);
        cpa16p(s + 1 * STAGE_ELEMS + s_off,     gAl,     true);
        cpa16p(s + 1 * STAGE_ELEMS + s_off + 8, gAl + 8, true);
        cpa16p(s + 2 * STAGE_ELEMS + s_off,     gBh,     bvalid);
        cpa16p(s + 2 * STAGE_ELEMS + s_off + 8, gBh + 8, bvalid);
        cpa16p(s + 3 * STAGE_ELEMS + s_off,     gBl,     bvalid);
        cpa16p(s + 3 * STAGE_ELEMS + s_off + 8, gBl + 8, bvalid);
    }
    cpa_commit();

    // fragment smem address components
    const int a_row = wm * 64 + (lane & 15);          // + mi*16
    const int a_colsel = ((lane >> 4) & 1) << 3;      // 0 or 8
    const int b_row0 = wn * 32 + (((lane >> 4) & 1) << 3) + (lane & 7); // + pair*16
    const int b_colsel = ((lane >> 3) & 1) << 3;

    for (int kt = 0; kt < nk; kt++) {
        cpa_wait_all();
        __syncthreads();

        if (kt + 1 < nk) {
            bf16* s = smem + ((kt + 1) & 1) * (4 * STAGE_ELEMS);
            const int ko = (kt + 1) << 5;
            cpa16p(s + 0 * STAGE_ELEMS + s_off,     gAh + ko,     true);
            cpa16p(s + 0 * STAGE_ELEMS + s_off + 8, gAh + ko + 8, true);
            cpa16p(s + 1 * STAGE_ELEMS + s_off,     gAl + ko,     true);
            cpa16p(s + 1 * STAGE_ELEMS + s_off + 8, gAl + ko + 8, true);
            cpa16p(s + 2 * STAGE_ELEMS + s_off,     gBh + ko,     bvalid);
            cpa16p(s + 2 * STAGE_ELEMS + s_off + 8, gBh + ko + 8, bvalid);
            cpa16p(s + 3 * STAGE_ELEMS + s_off,     gBl + ko,     bvalid);
            cpa16p(s + 3 * STAGE_ELEMS + s_off + 8, gBl + ko + 8, bvalid);
        }
        cpa_commit();

        bf16* st = smem + (kt & 1) * (4 * STAGE_ELEMS);
        const uint32_t sAh = (uint32_t)__cvta_generic_to_shared(st + 0 * STAGE_ELEMS);
        const uint32_t sAl = (uint32_t)__cvta_generic_to_shared(st + 1 * STAGE_ELEMS);
        const uint32_t sBh = (uint32_t)__cvta_generic_to_shared(st + 2 * STAGE_ELEMS);
        const uint32_t sBl = (uint32_t)__cvta_generic_to_shared(st + 3 * STAGE_ELEMS);

#pragma unroll
        for (int ks = 0; ks < 2; ks++) {
            const int koff = ks * 16;
            uint32_t ah[4][4], al[4][4], bh[4][2], bl[4][2];
#pragma unroll
            for (int mi = 0; mi < 4; mi++) {
                const uint32_t off =
                    ((a_row + mi * 16) * SKT + koff + a_colsel) * 2;
                ldm4(ah[mi], sAh + off);
                ldm4(al[mi], sAl + off);
            }
#pragma unroll
            for (int p = 0; p < 2; p++) {
                const uint32_t off =
                    ((b_row0 + p * 16) * SKT + koff + b_colsel) * 2;
                uint32_t th[4], tl[4];
                ldm4(th, sBh + off);
                ldm4(tl, sBl + off);
                bh[p * 2][0] = th[0]; bh[p * 2][1] = th[1];
                bh[p * 2 + 1][0] = th[2]; bh[p * 2 + 1][1] = th[3];
                bl[p * 2][0] = tl[0]; bl[p * 2][1] = tl[1];
                bl[p * 2 + 1][0] = tl[2]; bl[p * 2 + 1][1] = tl[3];
            }
#pragma unroll
            for (int mi = 0; mi < 4; mi++)
#pragma unroll
                for (int ni = 0; ni < 4; ni++) {
                    mma16816(acc[mi][ni], ah[mi], bh[ni]);
                    mma16816(acc[mi][ni], ah[mi], bl[ni]);
                    mma16816(acc[mi][ni], al[mi], bh[ni]);
                }
        }
        __syncthreads();
    }

    // epilogue
    const int trow = lane >> 2;
    const int tcol = (lane & 3) * 2;
#pragma unroll
    for (int mi = 0; mi < 4; mi++) {
        const size_t r0 = (size_t)bn + wm * 64 + mi * 16 + trow;
#pragma unroll
        for (int ni = 0; ni < 4; ni++) {
            const int col = bm + wn * 32 + ni * 8 + tcol;
            if (col < Mtot) {
                const float b0 = bias[col];
                const float b1 = bias[col + 1];
                float2 v0 = make_float2(acc[mi][ni][0] + b0, acc[mi][ni][1] + b1);
                float2 v1 = make_float2(acc[mi][ni][2] + b0, acc[mi][ni][3] + b1);
                *(float2*)&C[r0 * (size_t)ldc + col] = v0;
                *(float2*)&C[(r0 + 8) * (size_t)ldc + col] = v1;
            }
        }
    }
}

// ---------------------------------------------------------------------------
// Tiled sliding-window attention (flash style), strided q/k/v (fused qkv),
// writes bf16 hi/lo split at stride DD.
// ---------------------------------------------------------------------------
#define ATT_SMEM_FLOATS (4 * 64 * 64 + 3 * 64)

__global__ void __launch_bounds__(256)
attn_tile_kernel(const float* __restrict__ q, const float* __restrict__ k,
                 const float* __restrict__ v,
                 bf16* __restrict__ ohi, bf16* __restrict__ olo,
                 const int* __restrict__ winp, int qs)
{
    extern __shared__ float sm[];
    float* Qs  = sm;
    float* Kst = Qs + 64 * 64;
    float* Vs  = Kst + 64 * 64;
    float* Ss  = Vs + 64 * 64;
    float* m_s = Ss + 64 * 64;
    float* l_s = m_s + 64;
    float* sc_s = l_s + 64;

    const int q0 = blockIdx.x * 64;
    const int h  = blockIdx.y;
    const int b  = blockIdx.z;
    const int tid = threadIdx.x;
    const int win = *winp;

    const size_t base_q = ((size_t)(b * LL + q0)) * qs + h * HD;

    for (int i = tid; i < 1024; i += 256) {
        const int r = i >> 4;
        const int d4 = (i & 15) << 2;
        *(float4*)&Qs[r * 64 + d4] =
            *(const float4*)&q[base_q + (size_t)r * qs + d4];
    }
    if (tid < 64) { m_s[tid] = -INFINITY; l_s[tid] = 0.f; }

    const int ty = tid >> 4;
    const int tx = tid & 15;
    float accO[4][4];
#pragma unroll
    for (int i = 0; i < 4; i++)
#pragma unroll
        for (int j = 0; j < 4; j++) accO[i][j] = 0.f;

    int lo = q0 - win + 1;
    if (lo < 0) lo = 0;
    const int kt0 = lo >> 6;
    const int kt1 = q0 >> 6;

    __syncthreads();

    for (int kt = kt0; kt <= kt1; kt++) {
        const int j0 = kt << 6;
        const size_t base_k = ((size_t)(b * LL + j0)) * qs + h * HD;

        for (int i = tid; i < 1024; i += 256) {
            const int r = i >> 4;
            const int d4 = (i & 15) << 2;
            const float4 kv = *(const float4*)&k[base_k + (size_t)r * qs + d4];
            Kst[(d4 + 0) * 64 + r] = kv.x;
            Kst[(d4 + 1) * 64 + r] = kv.y;
            Kst[(d4 + 2) * 64 + r] = kv.z;
            Kst[(d4 + 3) * 64 + r] = kv.w;
            *(float4*)&Vs[r * 64 + d4] =
                *(const float4*)&v[base_k + (size_t)r * qs + d4];
        }
        __syncthreads();

        float accS[4][4];
#pragma unroll
        for (int i = 0; i < 4; i++)
#pragma unroll
            for (int j = 0; j < 4; j++) accS[i][j] = 0.f;

        for (int d = 0; d < 64; d += 4) {
            float4 qv[4];
#pragma unroll
            for (int i = 0; i < 4; i++)
                qv[i] = *(const float4*)&Qs[(ty * 4 + i) * 64 + d];
#pragma unroll
            for (int dd = 0; dd < 4; dd++) {
                const float4 kv = *(const float4*)&Kst[(d + dd) * 64 + tx * 4];
#pragma unroll
                for (int i = 0; i < 4; i++) {
                    const float qq = ((const float*)&qv[i])[dd];
                    accS[i][0] = fmaf(qq, kv.x, accS[i][0]);
                    accS[i][1] = fmaf(qq, kv.y, accS[i][1]);
                    accS[i][2] = fmaf(qq, kv.z, accS[i][2]);
                    accS[i][3] = fmaf(qq, kv.w, accS[i][3]);
                }
            }
        }

#pragma unroll
        for (int i = 0; i < 4; i++) {
            const int qi = q0 + ty * 4 + i;
#pragma unroll
            for (int j = 0; j < 4; j++) {
                const int jj = j0 + tx * 4 + j;
                const bool ok = (jj <= qi) && (qi - jj < win);
                Ss[(ty * 4 + i) * 64 + tx * 4 + j] =
                    ok ? accS[i][j] * 0.125f : -INFINITY;
            }
        }
        __syncthreads();

        {
            const int row = tid >> 2;
            const int part = tid & 3;
            float* srow = &Ss[row * 64 + part * 16];
            float tm = -INFINITY;
#pragma unroll
            for (int c = 0; c < 16; c++) tm = fmaxf(tm, srow[c]);
            tm = fmaxf(tm, __shfl_xor_sync(0xffffffffu, tm, 1));
            tm = fmaxf(tm, __shfl_xor_sync(0xffffffffu, tm, 2));

            const float mold = m_s[row];
            const float nm = fmaxf(mold, tm);
            float scale;
            float psum = 0.f;
            if (nm == -INFINITY) {
                scale = 1.f;
#pragma unroll
                for (int c = 0; c < 16; c++) srow[c] = 0.f;
            } else {
                scale = expf(mold - nm);
#pragma unroll
                for (int c = 0; c < 16; c++) {
                    const float p = expf(srow[c] - nm);
                    srow[c] = p;
                    psum += p;
                }
            }
            psum += __shfl_xor_sync(0xffffffffu, psum, 1);
            psum += __shfl_xor_sync(0xffffffffu, psum, 2);
            if (part == 0) {
                m_s[row] = nm;
                l_s[row] = l_s[row] * scale + psum;
                sc_s[row] = scale;
            }
        }
        __syncthreads();

#pragma unroll
        for (int i = 0; i < 4; i++) {
            const float s = sc_s[ty * 4 + i];
#pragma unroll
            for (int j = 0; j < 4; j++) accO[i][j] *= s;
        }
        for (int kk = 0; kk < 64; kk += 4) {
            float4 pv[4];
#pragma unroll
            for (int i = 0; i < 4; i++)
                pv[i] = *(const float4*)&Ss[(ty * 4 + i) * 64 + kk];
#pragma unroll
            for (int dd = 0; dd < 4; dd++) {
                const float4 vv = *(const float4*)&Vs[(kk + dd) * 64 + tx * 4];
#pragma unroll
                for (int i = 0; i < 4; i++) {
                    const float pp = ((const float*)&pv[i])[dd];
                    accO[i][0] = fmaf(pp, vv.x, accO[i][0]);
                    accO[i][1] = fmaf(pp, vv.y, accO[i][1]);
                    accO[i][2] = fmaf(pp, vv.z, accO[i][2]);
                    accO[i][3] = fmaf(pp, vv.w, accO[i][3]);
                }
            }
        }
        __syncthreads();
    }

#pragma unroll
    for (int i = 0; i < 4; i++) {
        const int r = ty * 4 + i;
        const float linv = 1.f / l_s[r];
#pragma unroll
        for (int j = 0; j < 4; j++) {
            float outv = accO[i][j] * linv;
            if (!isfinite(outv)) outv = 0.f;
            bf16 hi, lo2;
            split_f32(outv, hi, lo2);
            const size_t idx = ((size_t)(b * LL + q0 + r)) * DD + h * HD + tx * 4 + j;
            ohi[idx] = hi;
            olo[idx] = lo2;
        }
    }
}

// ---------------------------------------------------------------------------
// Launch
// ---------------------------------------------------------------------------
extern "C" void kernel_launch(void* const* d_in, const int* in_sizes, int n_in,
                              void* d_out, int out_size)
{
    const float* x    = (const float*)d_in[0];
    const float* wq_w = (const float*)d_in[1];
    const float* wq_b = (const float*)d_in[2];
    const float* wk_w = (const float*)d_in[3];
    const float* wk_b = (const float*)d_in[4];
    const float* wv_w = (const float*)d_in[5];
    const float* wv_b = (const float*)d_in[6];
    const float* wo_w = (const float*)d_in[7];
    const float* wo_b = (const float*)d_in[8];
    const float* q_nw = (const float*)d_in[9];
    const float* k_nw = (const float*)d_in[10];
    const float* s_nw = (const float*)d_in[11];
    const float* sp_nw= (const float*)d_in[12];
    const float* f_nw = (const float*)d_in[13];
    const float* fp_nw= (const float*)d_in[14];
    const float* w1_w = (const float*)d_in[15];
    const float* w1_b = (const float*)d_in[16];
    const float* w2_w = (const float*)d_in[17];
    const float* w2_b = (const float*)d_in[18];
    const float* w3_w = (const float*)d_in[19];
    const float* w3_b = (const float*)d_in[20];
    const int*   winp = (const int*)d_in[21];

    float* fbase = nullptr;
    cudaGetSymbolAddress((void**)&fbase, g_scratch);
    float* qkv = fbase;                       // [4096][3072]
    float* a   = fbase + 3 * SZ_D;
    float* h   = fbase + 4 * SZ_D;
    float* f   = fbase + 5 * SZ_D;
    float* z13 = fbase + 6 * SZ_D;            // [4096][6560]

    float* bqkv = nullptr;
    cudaGetSymbolAddress((void**)&bqkv, g_bias_qkv);
    float* bffn = nullptr;
    cudaGetSymbolAddress((void**)&bffn, g_bias_ffn);

    bf16* bbase = nullptr;
    cudaGetSymbolAddress((void**)&bbase, g_bscratch);
    bf16* xn_h = bbase + 0 * BSZ_ACT;
    bf16* xn_l = bbase + 1 * BSZ_ACT;
    bf16* at_h = bbase + 2 * BSZ_ACT;
    bf16* at_l = bbase + 3 * BSZ_ACT;
    bf16* hn_h = bbase + 4 * BSZ_ACT;
    bf16* hn_l = bbase + 5 * BSZ_ACT;
    bf16* g_h  = bbase + 6 * BSZ_ACT;
    bf16* g_l  = bbase + 6 * BSZ_ACT + BSZ_G;
    bf16* w_h  = bbase + 6 * BSZ_ACT + 2 * BSZ_G;
    bf16* w_l  = bbase + 6 * BSZ_ACT + 2 * BSZ_G + BSZ_W;

    float* out = (float*)d_out;

    cudaFuncSetAttribute(gemm_bf16x3,
                         cudaFuncAttributeMaxDynamicSharedMemorySize, GEMM_SMEM);

    // biases for fused GEMMs
    bias_concat_k<<<(II + 255) / 256, 256>>>(wq_b, wk_b, wv_b, w1_b, w3_b,
                                             bqkv, bffn);

    // 1) xn = rmsnorm(x, seq_norm_w) -> bf16 split
    rmsnorm_split_k<DD, 256><<<NROWS, 256>>>(x, s_nw, xn_h, xn_l);

    // 2) fused QKV projection
    {
        const int wN = DD * DD;
        conv_split_k<<<(wN + 255) / 256, 256>>>(wq_w, w_h, w_l, DD, DD, DD, DD);
        conv_split_k<<<(wN + 255) / 256, 256>>>(wk_w, w_h + (size_t)1024 * 1024,
                                                w_l + (size_t)1024 * 1024, DD, DD, DD, DD);
        conv_split_k<<<(wN + 255) / 256, 256>>>(wv_w, w_h + (size_t)2048 * 1024,
                                                w_l + (size_t)2048 * 1024, DD, DD, DD, DD);
        dim3 grid(QKVD / 128, NROWS / 128);
        gemm_bf16x3<<<grid, 256, GEMM_SMEM>>>(xn_h, xn_l, w_h, w_l, bqkv, qkv,
                                              QKVD, DD, QKVD);
    }

    // 3) per-head q/k rmsnorm (in-place on qkv)
    rmsnorm_head_k<<<NROWS * HH, 64>>>(qkv, q_nw, 0);
    rmsnorm_head_k<<<NROWS * HH, 64>>>(qkv, k_nw, 1024);

    // 4) attention -> bf16 split output
    {
        const size_t smem_bytes = (size_t)ATT_SMEM_FLOATS * sizeof(float);
        cudaFuncSetAttribute(attn_tile_kernel,
                             cudaFuncAttributeMaxDynamicSharedMemorySize,
                             (int)smem_bytes);
        dim3 grid(LL / 64, HH, BB);
        attn_tile_kernel<<<grid, 256, smem_bytes>>>(qkv, qkv + 1024, qkv + 2048,
                                                    at_h, at_l, winp, QKVD);
    }

    // 5) output projection
    {
        const int wN = DD * DD;
        conv_split_k<<<(wN + 255) / 256, 256>>>(wo_w, w_h, w_l, DD, DD, DD, DD);
        dim3 grid(DD / 128, NROWS / 128);
        gemm_bf16x3<<<grid, 256, GEMM_SMEM>>>(at_h, at_l, w_h, w_l, wo_b, a,
                                              DD, DD, DD);
    }

    // 6) h = x + rmsnorm(a, seq_post_norm_w)
    rmsnorm_k<DD, 256><<<NROWS, 256>>>(a, sp_nw, x, h);

    // 7) hn = rmsnorm(h, ffn_norm_w) -> bf16 split
    rmsnorm_split_k<DD, 256><<<NROWS, 256>>>(h, f_nw, hn_h, hn_l);

    // 8) fused w1||w3 GEMM -> z13
    {
        const size_t wN1 = (size_t)II * DD;
        conv_split_k<<<(int)((wN1 + 255) / 256), 256>>>(w1_w, w_h, w_l,
                                                        II, DD, II, DD);
        const size_t off = (size_t)II * DD;
        const size_t wN2 = (size_t)(I2P - II) * DD;
        conv_split_k<<<(int)((wN2 + 255) / 256), 256>>>(w3_w, w_h + off, w_l + off,
                                                        II, DD, I2P - II, DD);
        dim3 grid(I2P / 128, NROWS / 128);
        gemm_bf16x3<<<grid, 256, GEMM_SMEM>>>(hn_h, hn_l, w_h, w_l, bffn, z13,
                                              I2, DD, I2);
    }

    // 9) g = silu(z1)*z3 -> bf16 split (stride IKP, zero pad)
    {
        size_t n = (size_t)NROWS * IKP;
        silu_split_k<<<(int)((n + 255) / 256), 256>>>(z13, g_h, g_l);
    }

    // 10) f = g @ w2^T + b2  (K = IKP, weight K-padded)
    {
        const size_t wN = (size_t)DD * IKP;
        conv_split_k<<<(int)((wN + 255) / 256), 256>>>(w2_w, w_h, w_l,
                                                       DD, II, DD, IKP);
        dim3 grid(DD / 128, NROWS / 128);
        gemm_bf16x3<<<grid, 256, GEMM_SMEM>>>(g_h, g_l, w_h, w_l, w2_b, f,
                                              DD, IKP, DD);
    }

    // 11) out = h + rmsnorm(f, ffn_post_norm_w)
    rmsnorm_k<DD, 256><<<NROWS, 256>>>(f, fp_nw, h, out);
}

// round 9
// speedup vs baseline: 1.4837x; 1.0324x over previous
#include <cuda_runtime.h>
#include <cuda_bf16.h>
#include <math.h>
#include <stdint.h>

typedef __nv_bfloat16 bf16;

// ---------------------------------------------------------------------------
// Problem constants
// ---------------------------------------------------------------------------
#define BB 4
#define LL 1024
#define DD 1024
#define HH 16
#define HD 64
#define II 3280
#define I2 6560                // 2*II (interleaved w1/w3 output cols)
#define I2P 6656               // I2 padded to 128
#define IKP 3328               // II padded to 128 (w2 K / g stride)
#define QKVD 3072              // fused qkv row width
#define NROWS (BB * LL)        // 4096
#define EPSV 1e-5f

#define SZ_D ((size_t)NROWS * DD)
#define SZ_I ((size_t)NROWS * II)

// fp32 scratch: qkv(3*SZ_D), a, h, f
__device__ float g_scratch[6 * SZ_D];
__device__ float g_bias_qkv[QKVD];
__device__ float g_bias_ffn[I2P];

// bf16 scratch (hi/lo pairs)
#define BSZ_ACT ((size_t)NROWS * DD)
#define BSZ_G   ((size_t)NROWS * IKP)
#define BSZ_W   ((size_t)I2P * 1024)
__device__ bf16 g_bscratch[6 * BSZ_ACT + 2 * BSZ_G + 2 * BSZ_W];

// ---------------------------------------------------------------------------
// helpers
// ---------------------------------------------------------------------------
__device__ __forceinline__ void split_f32(float v, bf16& hi, bf16& lo) {
    hi = __float2bfloat16(v);
    lo = __float2bfloat16(v - __bfloat162float(hi));
}

__device__ __forceinline__ void cpa16p(bf16* dst, const bf16* src, bool valid) {
    uint32_t d = (uint32_t)__cvta_generic_to_shared(dst);
    int sz = valid ? 16 : 0;
    asm volatile("cp.async.ca.shared.global [%0], [%1], 16, %2;\n"
                 :: "r"(d), "l"(src), "r"(sz));
}
__device__ __forceinline__ void cpa_commit() {
    asm volatile("cp.async.commit_group;\n" ::: "memory");
}
__device__ __forceinline__ void cpa_wait_all() {
    asm volatile("cp.async.wait_group 0;\n" ::: "memory");
}

__device__ __forceinline__ void ldm4(uint32_t* r, uint32_t addr) {
    asm volatile("ldmatrix.sync.aligned.m8n8.x4.shared.b16 {%0,%1,%2,%3}, [%4];\n"
                 : "=r"(r[0]), "=r"(r[1]), "=r"(r[2]), "=r"(r[3]) : "r"(addr));
}

__device__ __forceinline__ void mma16816(float* d, const uint32_t* a, const uint32_t* b) {
    asm volatile(
        "mma.sync.aligned.m16n8k16.row.col.f32.bf16.bf16.f32 "
        "{%0,%1,%2,%3}, {%4,%5,%6,%7}, {%8,%9}, {%0,%1,%2,%3};\n"
        : "+f"(d[0]), "+f"(d[1]), "+f"(d[2]), "+f"(d[3])
        : "r"(a[0]), "r"(a[1]), "r"(a[2]), "r"(a[3]), "r"(b[0]), "r"(b[1]));
}

// pack 8 floats into 8 bf16 (hi) + 8 bf16 (lo), store as uint4
__device__ __forceinline__ void store_split8(bf16* hi, bf16* lo, const float* v) {
    bf16 hbuf[8], lbuf[8];
#pragma unroll
    for (int i = 0; i < 8; i++) split_f32(v[i], hbuf[i], lbuf[i]);
    *(uint4*)hi = *(const uint4*)hbuf;
    *(uint4*)lo = *(const uint4*)lbuf;
}

// ---------------------------------------------------------------------------
// RMSNorm (fp32 out, optional residual)
// ---------------------------------------------------------------------------
template <int W, int T>
__global__ void rmsnorm_k(const float* __restrict__ in,
                          const float* __restrict__ w,
                          const float* __restrict__ resid,
                          float* __restrict__ out)
{
    constexpr int PER = W / T;
    const size_t row = blockIdx.x;
    const float* xr = in + row * (size_t)W;
    float vals[PER];
    float ss = 0.f;
#pragma unroll
    for (int i = 0; i < PER; i++) {
        float vv = xr[threadIdx.x + i * T];
        vv = fminf(fmaxf(vv, -10000.f), 10000.f);
        vals[i] = vv;
        ss += vv * vv;
    }
    __shared__ float red[T];
    red[threadIdx.x] = ss;
    __syncthreads();
#pragma unroll
    for (int s = T / 2; s > 0; s >>= 1) {
        if (threadIdx.x < s) red[threadIdx.x] += red[threadIdx.x + s];
        __syncthreads();
    }
    const float mean = red[0] / (float)W;
    const float inv = 1.f / sqrtf(fmaxf(mean, EPSV) + EPSV);
#pragma unroll
    for (int i = 0; i < PER; i++) {
        const int c = threadIdx.x + i * T;
        float o = vals[i] * inv * w[c];
        if (!isfinite(o)) o = 0.f;
        if (resid) o += resid[row * (size_t)W + c];
        out[row * (size_t)W + c] = o;
    }
}

// RMSNorm writing bf16 hi/lo split
template <int W, int T>
__global__ void rmsnorm_split_k(const float* __restrict__ in,
                                const float* __restrict__ w,
                                bf16* __restrict__ ohi,
                                bf16* __restrict__ olo)
{
    constexpr int PER = W / T;
    const size_t row = blockIdx.x;
    const float* xr = in + row * (size_t)W;
    float vals[PER];
    float ss = 0.f;
#pragma unroll
    for (int i = 0; i < PER; i++) {
        float vv = xr[threadIdx.x + i * T];
        vv = fminf(fmaxf(vv, -10000.f), 10000.f);
        vals[i] = vv;
        ss += vv * vv;
    }
    __shared__ float red[T];
    red[threadIdx.x] = ss;
    __syncthreads();
#pragma unroll
    for (int s = T / 2; s > 0; s >>= 1) {
        if (threadIdx.x < s) red[threadIdx.x] += red[threadIdx.x + s];
        __syncthreads();
    }
    const float mean = red[0] / (float)W;
    const float inv = 1.f / sqrtf(fmaxf(mean, EPSV) + EPSV);
#pragma unroll
    for (int i = 0; i < PER; i++) {
        const int c = threadIdx.x + i * T;
        float o = vals[i] * inv * w[c];
        if (!isfinite(o)) o = 0.f;
        bf16 hi, lo;
        split_f32(o, hi, lo);
        ohi[row * (size_t)W + c] = hi;
        olo[row * (size_t)W + c] = lo;
    }
}

// per-head rmsnorm (in-place on strided qkv buffer; 64 threads)
__global__ void rmsnorm_head_k(float* __restrict__ qkv,
                               const float* __restrict__ w, int colOff)
{
    const int ri = blockIdx.x;
    const int r = ri >> 4;
    const int h = ri & 15;
    float* xr = qkv + (size_t)r * QKVD + colOff + h * HD;
    const int t = threadIdx.x;
    float vv = xr[t];
    vv = fminf(fmaxf(vv, -10000.f), 10000.f);
    __shared__ float red[64];
    red[t] = vv * vv;
    __syncthreads();
#pragma unroll
    for (int s = 32; s > 0; s >>= 1) {
        if (t < s) red[t] += red[t + s];
        __syncthreads();
    }
    const float mean = red[0] / 64.f;
    const float inv = 1.f / sqrtf(fmaxf(mean, EPSV) + EPSV);
    float o = vv * inv * w[t];
    if (!isfinite(o)) o = 0.f;
    xr[t] = o;
}

// ---------------------------------------------------------------------------
// Vectorized weight split (8 elems/thread). KP, K0 multiples of 8.
// ---------------------------------------------------------------------------
__global__ void conv_split8_k(const float* __restrict__ src,
                              bf16* __restrict__ hi, bf16* __restrict__ lo,
                              int rows, int K0, int rowsPad, int KP)
{
    size_t i8 = ((size_t)blockIdx.x * blockDim.x + threadIdx.x) * 8;
    size_t n = (size_t)rowsPad * KP;
    if (i8 >= n) return;
    int r = (int)(i8 / KP);
    int c = (int)(i8 % KP);
    float v[8];
    if (r < rows && c + 8 <= K0) {
        const float* s = src + (size_t)r * K0 + c;
        *(float4*)&v[0] = *(const float4*)s;
        *(float4*)&v[4] = *(const float4*)(s + 4);
    } else {
#pragma unroll
        for (int i = 0; i < 8; i++) {
            int cc = c + i;
            v[i] = (r < rows && cc < K0) ? src[(size_t)r * K0 + cc] : 0.f;
        }
    }
    store_split8(hi + i8, lo + i8, v);
}

// Interleaved w1/w3 split: dst row 2i <- w1[i], row 2i+1 <- w3[i]; K=1024.
// rowsPad = I2P (zero tail).
__global__ void conv_split_ilv8_k(const float* __restrict__ w1,
                                  const float* __restrict__ w3,
                                  bf16* __restrict__ hi, bf16* __restrict__ lo)
{
    size_t i8 = ((size_t)blockIdx.x * blockDim.x + threadIdx.x) * 8;
    size_t n = (size_t)I2P * DD;
    if (i8 >= n) return;
    int r = (int)(i8 / DD);
    int c = (int)(i8 % DD);
    int sr = r >> 1;
    float v[8];
    if (sr < II) {
        const float* s = ((r & 1) ? w3 : w1) + (size_t)sr * DD + c;
        *(float4*)&v[0] = *(const float4*)s;
        *(float4*)&v[4] = *(const float4*)(s + 4);
    } else {
#pragma unroll
        for (int i = 0; i < 8; i++) v[i] = 0.f;
    }
    store_split8(hi + i8, lo + i8, v);
}

// bias concat: qkv bias + interleaved ffn bias (zero-padded to I2P)
__global__ void bias_concat_k(const float* qb, const float* kb, const float* vb,
                              const float* b1, const float* b3,
                              float* outQKV, float* outFFN)
{
    int i = blockIdx.x * blockDim.x + threadIdx.x;
    if (i < 1024) {
        outQKV[i] = qb[i];
        outQKV[1024 + i] = kb[i];
        outQKV[2048 + i] = vb[i];
    }
    if (i < I2P) {
        int sr = i >> 1;
        outFFN[i] = (sr < II) ? ((i & 1) ? b3[sr] : b1[sr]) : 0.f;
    }
}

// ---------------------------------------------------------------------------
// bf16x3 tensor-core GEMM (NT): C[n,m] = sum_k A[n,k]*B[m,k] + bias[m]
// CTA 128x128, BK=32, 256 threads (8 warps, 2x4; 64x32/warp), cp.async
// double-buffered, pad-40 rows, ldmatrix, mma.sync bf16, fp32 accum.
// fuse_silu==1: output cols are interleaved (z1,z3) pairs; epilogue computes
// g = silu(z1)*z3 and writes bf16 hi/lo split at [row*ldg + col/2].
// ---------------------------------------------------------------------------
#define SKT 40
#define STAGE_ELEMS (128 * SKT)
#define GEMM_SMEM (2 * 4 * STAGE_ELEMS * 2)        // 81920 bytes

__global__ void __launch_bounds__(256)
gemm_bf16x3(const bf16* __restrict__ Ah, const bf16* __restrict__ Al,
            const bf16* __restrict__ Bh, const bf16* __restrict__ Bl,
            const float* __restrict__ bias, float* __restrict__ C,
            int Mtot, int K, int ldc,
            int fuse_silu, bf16* __restrict__ Ghi, bf16* __restrict__ Glo,
            int ldg)
{
    extern __shared__ __align__(16) bf16 smem[];

    const int tid = threadIdx.x;
    const int lane = tid & 31;
    const int wid = tid >> 5;
    const int wm = wid & 1;
    const int wn = wid >> 1;

    const int bm = blockIdx.x * 128;
    const int bn = blockIdx.y * 128;

    const int ldr = tid >> 1;
    const int ldcol = (tid & 1) * 16;

    const bf16* gAh = Ah + (size_t)(bn + ldr) * K + ldcol;
    const bf16* gAl = Al + (size_t)(bn + ldr) * K + ldcol;
    const bool bvalid = (bm + ldr) < Mtot;
    const bf16* gBh = Bh + (size_t)(bm + ldr) * K + ldcol;
    const bf16* gBl = Bl + (size_t)(bm + ldr) * K + ldcol;

    const int s_off = ldr * SKT + ldcol;

    float acc[4][4][4];
#pragma unroll
    for (int i = 0; i < 4; i++)
#pragma unroll
        for (int j = 0; j < 4; j++)
#pragma unroll
            for (int r = 0; r < 4; r++) acc[i][j][r] = 0.f;

    const int nk = K >> 5;

    {
        bf16* s = smem;
        cpa16p(s + 0 * STAGE_ELEMS + s_off,     gAh,     true);
        cpa16p(s + 0 * STAGE_ELEMS + s_off + 8, gAh + 8, true);
        cpa16p(s + 1 * STAGE_ELEMS + s_off,     gAl,     true);
        cpa16p(s + 1 * STAGE_ELEMS + s_off + 8, gAl + 8, true);
        cpa16p(s + 2 * STAGE_ELEMS + s_off,     gBh,     bvalid);
        cpa16p(s + 2 * STAGE_ELEMS + s_off + 8, gBh + 8, bvalid);
        cpa16p(s + 3 * STAGE_ELEMS + s_off,     gBl,     bvalid);
        cpa16p(s + 3 * STAGE_ELEMS + s_off + 8, gBl + 8, bvalid);
    }
    cpa_commit();

    const int a_row = wm * 64 + (lane & 15);
    const int a_colsel = ((lane >> 4) & 1) << 3;
    const int b_row0 = wn * 32 + (((lane >> 4) & 1) << 3) + (lane & 7);
    const int b_colsel = ((lane >> 3) & 1) << 3;

    for (int kt = 0; kt < nk; kt++) {
        cpa_wait_all();
        __syncthreads();

        if (kt + 1 < nk) {
            bf16* s = smem + ((kt + 1) & 1) * (4 * STAGE_ELEMS);
            const int ko = (kt + 1) << 5;
            cpa16p(s + 0 * STAGE_ELEMS + s_off,     gAh + ko,     true);
            cpa16p(s + 0 * STAGE_ELEMS + s_off + 8, gAh + ko + 8, true);
            cpa16p(s + 1 * STAGE_ELEMS + s_off,     gAl + ko,     true);
            cpa16p(s + 1 * STAGE_ELEMS + s_off + 8, gAl + ko + 8, true);
            cpa16p(s + 2 * STAGE_ELEMS + s_off,     gBh + ko,     bvalid);
            cpa16p(s + 2 * STAGE_ELEMS + s_off + 8, gBh + ko + 8, bvalid);
            cpa16p(s + 3 * STAGE_ELEMS + s_off,     gBl + ko,     bvalid);
            cpa16p(s + 3 * STAGE_ELEMS + s_off + 8, gBl + ko + 8, bvalid);
        }
        cpa_commit();

        bf16* st = smem + (kt & 1) * (4 * STAGE_ELEMS);
        const uint32_t sAh = (uint32_t)__cvta_generic_to_shared(st + 0 * STAGE_ELEMS);
        const uint32_t sAl = (uint32_t)__cvta_generic_to_shared(st + 1 * STAGE_ELEMS);
        const uint32_t sBh = (uint32_t)__cvta_generic_to_shared(st + 2 * STAGE_ELEMS);
        const uint32_t sBl = (uint32_t)__cvta_generic_to_shared(st + 3 * STAGE_ELEMS);

#pragma unroll
        for (int ks = 0; ks < 2; ks++) {
            const int koff = ks * 16;
            uint32_t ah[4][4], al[4][4], bh[4][2], bl[4][2];
#pragma unroll
            for (int mi = 0; mi < 4; mi++) {
                const uint32_t off =
                    ((a_row + mi * 16) * SKT + koff + a_colsel) * 2;
                ldm4(ah[mi], sAh + off);
                ldm4(al[mi], sAl + off);
            }
#pragma unroll
            for (int p = 0; p < 2; p++) {
                const uint32_t off =
                    ((b_row0 + p * 16) * SKT + koff + b_colsel) * 2;
                uint32_t th[4], tl[4];
                ldm4(th, sBh + off);
                ldm4(tl, sBl + off);
                bh[p * 2][0] = th[0]; bh[p * 2][1] = th[1];
                bh[p * 2 + 1][0] = th[2]; bh[p * 2 + 1][1] = th[3];
                bl[p * 2][0] = tl[0]; bl[p * 2][1] = tl[1];
                bl[p * 2 + 1][0] = tl[2]; bl[p * 2 + 1][1] = tl[3];
            }
#pragma unroll
            for (int mi = 0; mi < 4; mi++)
#pragma unroll
                for (int ni = 0; ni < 4; ni++) {
                    mma16816(acc[mi][ni], ah[mi], bh[ni]);
                    mma16816(acc[mi][ni], ah[mi], bl[ni]);
                    mma16816(acc[mi][ni], al[mi], bh[ni]);
                }
        }
        __syncthreads();
    }

    // epilogue
    const int trow = lane >> 2;
    const int tcol = (lane & 3) * 2;
    if (!fuse_silu) {
#pragma unroll
        for (int mi = 0; mi < 4; mi++) {
            const size_t r0 = (size_t)bn + wm * 64 + mi * 16 + trow;
#pragma unroll
            for (int ni = 0; ni < 4; ni++) {
                const int col = bm + wn * 32 + ni * 8 + tcol;
                if (col < Mtot) {
                    const float b0 = bias[col];
                    const float b1 = bias[col + 1];
                    float2 v0 = make_float2(acc[mi][ni][0] + b0, acc[mi][ni][1] + b1);
                    float2 v1 = make_float2(acc[mi][ni][2] + b0, acc[mi][ni][3] + b1);
                    *(float2*)&C[r0 * (size_t)ldc + col] = v0;
                    *(float2*)&C[(r0 + 8) * (size_t)ldc + col] = v1;
                }
            }
        }
    } else {
        // cols are interleaved (z1,z3) pairs; compute silu(z1)*z3, split-store
#pragma unroll
        for (int mi = 0; mi < 4; mi++) {
            const size_t r0 = (size_t)bn + wm * 64 + mi * 16 + trow;
#pragma unroll
            for (int ni = 0; ni < 4; ni++) {
                const int col = bm + wn * 32 + ni * 8 + tcol;   // even
                const int gcol = col >> 1;
                const float b0 = bias[col];
                const float b1 = bias[col + 1];
                {
                    const float z1 = acc[mi][ni][0] + b0;
                    const float z3 = acc[mi][ni][1] + b1;
                    const float g = (z1 / (1.f + expf(-z1))) * z3;
                    bf16 hi, lo;
                    split_f32(g, hi, lo);
                    Ghi[r0 * (size_t)ldg + gcol] = hi;
                    Glo[r0 * (size_t)ldg + gcol] = lo;
                }
                {
                    const float z1 = acc[mi][ni][2] + b0;
                    const float z3 = acc[mi][ni][3] + b1;
                    const float g = (z1 / (1.f + expf(-z1))) * z3;
                    bf16 hi, lo;
                    split_f32(g, hi, lo);
                    Ghi[(r0 + 8) * (size_t)ldg + gcol] = hi;
                    Glo[(r0 + 8) * (size_t)ldg + gcol] = lo;
                }
            }
        }
    }
}

// ---------------------------------------------------------------------------
// Tiled sliding-window attention (flash style), strided q/k/v (fused qkv),
// writes bf16 hi/lo split at stride DD.
// ---------------------------------------------------------------------------
#define ATT_SMEM_FLOATS (4 * 64 * 64 + 3 * 64)

__global__ void __launch_bounds__(256)
attn_tile_kernel(const float* __restrict__ q, const float* __restrict__ k,
                 const float* __restrict__ v,
                 bf16* __restrict__ ohi, bf16* __restrict__ olo,
                 const int* __restrict__ winp, int qs)
{
    extern __shared__ float sm[];
    float* Qs  = sm;
    float* Kst = Qs + 64 * 64;
    float* Vs  = Kst + 64 * 64;
    float* Ss  = Vs + 64 * 64;
    float* m_s = Ss + 64 * 64;
    float* l_s = m_s + 64;
    float* sc_s = l_s + 64;

    const int q0 = blockIdx.x * 64;
    const int h  = blockIdx.y;
    const int b  = blockIdx.z;
    const int tid = threadIdx.x;
    const int win = *winp;

    const size_t base_q = ((size_t)(b * LL + q0)) * qs + h * HD;

    for (int i = tid; i < 1024; i += 256) {
        const int r = i >> 4;
        const int d4 = (i & 15) << 2;
        *(float4*)&Qs[r * 64 + d4] =
            *(const float4*)&q[base_q + (size_t)r * qs + d4];
    }
    if (tid < 64) { m_s[tid] = -INFINITY; l_s[tid] = 0.f; }

    const int ty = tid >> 4;
    const int tx = tid & 15;
    float accO[4][4];
#pragma unroll
    for (int i = 0; i < 4; i++)
#pragma unroll
        for (int j = 0; j < 4; j++) accO[i][j] = 0.f;

    int lo = q0 - win + 1;
    if (lo < 0) lo = 0;
    const int kt0 = lo >> 6;
    const int kt1 = q0 >> 6;

    __syncthreads();

    for (int kt = kt0; kt <= kt1; kt++) {
        const int j0 = kt << 6;
        const size_t base_k = ((size_t)(b * LL + j0)) * qs + h * HD;

        for (int i = tid; i < 1024; i += 256) {
            const int r = i >> 4;
            const int d4 = (i & 15) << 2;
            const float4 kv = *(const float4*)&k[base_k + (size_t)r * qs + d4];
            Kst[(d4 + 0) * 64 + r] = kv.x;
            Kst[(d4 + 1) * 64 + r] = kv.y;
            Kst[(d4 + 2) * 64 + r] = kv.z;
            Kst[(d4 + 3) * 64 + r] = kv.w;
            *(float4*)&Vs[r * 64 + d4] =
                *(const float4*)&v[base_k + (size_t)r * qs + d4];
        }
        __syncthreads();

        float accS[4][4];
#pragma unroll
        for (int i = 0; i < 4; i++)
#pragma unroll
            for (int j = 0; j < 4; j++) accS[i][j] = 0.f;

        for (int d = 0; d < 64; d += 4) {
            float4 qv[4];
#pragma unroll
            for (int i = 0; i < 4; i++)
                qv[i] = *(const float4*)&Qs[(ty * 4 + i) * 64 + d];
#pragma unroll
            for (int dd = 0; dd < 4; dd++) {
                const float4 kv = *(const float4*)&Kst[(d + dd) * 64 + tx * 4];
#pragma unroll
                for (int i = 0; i < 4; i++) {
                    const float qq = ((const float*)&qv[i])[dd];
                    accS[i][0] = fmaf(qq, kv.x, accS[i][0]);
                    accS[i][1] = fmaf(qq, kv.y, accS[i][1]);
                    accS[i][2] = fmaf(qq, kv.z, accS[i][2]);
                    accS[i][3] = fmaf(qq, kv.w, accS[i][3]);
                }
            }
        }

#pragma unroll
        for (int i = 0; i < 4; i++) {
            const int qi = q0 + ty * 4 + i;
#pragma unroll
            for (int j = 0; j < 4; j++) {
                const int jj = j0 + tx * 4 + j;
                const bool ok = (jj <= qi) && (qi - jj < win);
                Ss[(ty * 4 + i) * 64 + tx * 4 + j] =
                    ok ? accS[i][j] * 0.125f : -INFINITY;
            }
        }
        __syncthreads();

        {
            const int row = tid >> 2;
            const int part = tid & 3;
            float* srow = &Ss[row * 64 + part * 16];
            float tm = -INFINITY;
#pragma unroll
            for (int c = 0; c < 16; c++) tm = fmaxf(tm, srow[c]);
            tm = fmaxf(tm, __shfl_xor_sync(0xffffffffu, tm, 1));
            tm = fmaxf(tm, __shfl_xor_sync(0xffffffffu, tm, 2));

            const float mold = m_s[row];
            const float nm = fmaxf(mold, tm);
            float scale;
            float psum = 0.f;
            if (nm == -INFINITY) {
                scale = 1.f;
#pragma unroll
                for (int c = 0; c < 16; c++) srow[c] = 0.f;
            } else {
                scale = expf(mold - nm);
#pragma unroll
                for (int c = 0; c < 16; c++) {
                    const float p = expf(srow[c] - nm);
                    srow[c] = p;
                    psum += p;
                }
            }
            psum += __shfl_xor_sync(0xffffffffu, psum, 1);
            psum += __shfl_xor_sync(0xffffffffu, psum, 2);
            if (part == 0) {
                m_s[row] = nm;
                l_s[row] = l_s[row] * scale + psum;
                sc_s[row] = scale;
            }
        }
        __syncthreads();

#pragma unroll
        for (int i = 0; i < 4; i++) {
            const float s = sc_s[ty * 4 + i];
#pragma unroll
            for (int j = 0; j < 4; j++) accO[i][j] *= s;
        }
        for (int kk = 0; kk < 64; kk += 4) {
            float4 pv[4];
#pragma unroll
            for (int i = 0; i < 4; i++)
                pv[i] = *(const float4*)&Ss[(ty * 4 + i) * 64 + kk];
#pragma unroll
            for (int dd = 0; dd < 4; dd++) {
                const float4 vv = *(const float4*)&Vs[(kk + dd) * 64 + tx * 4];
#pragma unroll
                for (int i = 0; i < 4; i++) {
                    const float pp = ((const float*)&pv[i])[dd];
                    accO[i][0] = fmaf(pp, vv.x, accO[i][0]);
                    accO[i][1] = fmaf(pp, vv.y, accO[i][1]);
                    accO[i][2] = fmaf(pp, vv.z, accO[i][2]);
                    accO[i][3] = fmaf(pp, vv.w, accO[i][3]);
                }
            }
        }
        __syncthreads();
    }

#pragma unroll
    for (int i = 0; i < 4; i++) {
        const int r = ty * 4 + i;
        const float linv = 1.f / l_s[r];
#pragma unroll
        for (int j = 0; j < 4; j++) {
            float outv = accO[i][j] * linv;
            if (!isfinite(outv)) outv = 0.f;
            bf16 hi, lo2;
            split_f32(outv, hi, lo2);
            const size_t idx = ((size_t)(b * LL + q0 + r)) * DD + h * HD + tx * 4 + j;
            ohi[idx] = hi;
            olo[idx] = lo2;
        }
    }
}

// ---------------------------------------------------------------------------
// Launch
// ---------------------------------------------------------------------------
extern "C" void kernel_launch(void* const* d_in, const int* in_sizes, int n_in,
                              void* d_out, int out_size)
{
    const float* x    = (const float*)d_in[0];
    const float* wq_w = (const float*)d_in[1];
    const float* wq_b = (const float*)d_in[2];
    const float* wk_w = (const float*)d_in[3];
    const float* wk_b = (const float*)d_in[4];
    const float* wv_w = (const float*)d_in[5];
    const float* wv_b = (const float*)d_in[6];
    const float* wo_w = (const float*)d_in[7];
    const float* wo_b = (const float*)d_in[8];
    const float* q_nw = (const float*)d_in[9];
    const float* k_nw = (const float*)d_in[10];
    const float* s_nw = (const float*)d_in[11];
    const float* sp_nw= (const float*)d_in[12];
    const float* f_nw = (const float*)d_in[13];
    const float* fp_nw= (const float*)d_in[14];
    const float* w1_w = (const float*)d_in[15];
    const float* w1_b = (const float*)d_in[16];
    const float* w2_w = (const float*)d_in[17];
    const float* w2_b = (const float*)d_in[18];
    const float* w3_w = (const float*)d_in[19];
    const float* w3_b = (const float*)d_in[20];
    const int*   winp = (const int*)d_in[21];

    float* fbase = nullptr;
    cudaGetSymbolAddress((void**)&fbase, g_scratch);
    float* qkv = fbase;                       // [4096][3072]
    float* a   = fbase + 3 * SZ_D;
    float* h   = fbase + 4 * SZ_D;
    float* f   = fbase + 5 * SZ_D;

    float* bqkv = nullptr;
    cudaGetSymbolAddress((void**)&bqkv, g_bias_qkv);
    float* bffn = nullptr;
    cudaGetSymbolAddress((void**)&bffn, g_bias_ffn);

    bf16* bbase = nullptr;
    cudaGetSymbolAddress((void**)&bbase, g_bscratch);
    bf16* xn_h = bbase + 0 * BSZ_ACT;
    bf16* xn_l = bbase + 1 * BSZ_ACT;
    bf16* at_h = bbase + 2 * BSZ_ACT;
    bf16* at_l = bbase + 3 * BSZ_ACT;
    bf16* hn_h = bbase + 4 * BSZ_ACT;
    bf16* hn_l = bbase + 5 * BSZ_ACT;
    bf16* g_h  = bbase + 6 * BSZ_ACT;
    bf16* g_l  = bbase + 6 * BSZ_ACT + BSZ_G;
    bf16* w_h  = bbase + 6 * BSZ_ACT + 2 * BSZ_G;
    bf16* w_l  = bbase + 6 * BSZ_ACT + 2 * BSZ_G + BSZ_W;

    float* out = (float*)d_out;

    cudaFuncSetAttribute(gemm_bf16x3,
                         cudaFuncAttributeMaxDynamicSharedMemorySize, GEMM_SMEM);

    // biases for fused GEMMs
    bias_concat_k<<<(I2P + 255) / 256, 256>>>(wq_b, wk_b, wv_b, w1_b, w3_b,
                                              bqkv, bffn);

    // 1) xn = rmsnorm(x, seq_norm_w) -> bf16 split
    rmsnorm_split_k<DD, 256><<<NROWS, 256>>>(x, s_nw, xn_h, xn_l);

    // 2) fused QKV projection
    {
        const size_t wN8 = (size_t)DD * DD / 8;
        conv_split8_k<<<(int)((wN8 + 255) / 256), 256>>>(wq_w, w_h, w_l, DD, DD, DD, DD);
        conv_split8_k<<<(int)((wN8 + 255) / 256), 256>>>(wk_w, w_h + (size_t)1024 * 1024,
                                                         w_l + (size_t)1024 * 1024, DD, DD, DD, DD);
        conv_split8_k<<<(int)((wN8 + 255) / 256), 256>>>(wv_w, w_h + (size_t)2048 * 1024,
                                                         w_l + (size_t)2048 * 1024, DD, DD, DD, DD);
        dim3 grid(QKVD / 128, NROWS / 128);
        gemm_bf16x3<<<grid, 256, GEMM_SMEM>>>(xn_h, xn_l, w_h, w_l, bqkv, qkv,
                                              QKVD, DD, QKVD, 0, nullptr, nullptr, 0);
    }

    // 3) per-head q/k rmsnorm (in-place on qkv)
    rmsnorm_head_k<<<NROWS * HH, 64>>>(qkv, q_nw, 0);
    rmsnorm_head_k<<<NROWS * HH, 64>>>(qkv, k_nw, 1024);

    // 4) attention -> bf16 split output
    {
        const size_t smem_bytes = (size_t)ATT_SMEM_FLOATS * sizeof(float);
        cudaFuncSetAttribute(attn_tile_kernel,
                             cudaFuncAttributeMaxDynamicSharedMemorySize,
                             (int)smem_bytes);
        dim3 grid(LL / 64, HH, BB);
        attn_tile_kernel<<<grid, 256, smem_bytes>>>(qkv, qkv + 1024, qkv + 2048,
                                                    at_h, at_l, winp, QKVD);
    }

    // 5) output projection
    {
        const size_t wN8 = (size_t)DD * DD / 8;
        conv_split8_k<<<(int)((wN8 + 255) / 256), 256>>>(wo_w, w_h, w_l, DD, DD, DD, DD);
        dim3 grid(DD / 128, NROWS / 128);
        gemm_bf16x3<<<grid, 256, GEMM_SMEM>>>(at_h, at_l, w_h, w_l, wo_b, a,
                                              DD, DD, DD, 0, nullptr, nullptr, 0);
    }

    // 6) h = x + rmsnorm(a, seq_post_norm_w)
    rmsnorm_k<DD, 256><<<NROWS, 256>>>(a, sp_nw, x, h);

    // 7) hn = rmsnorm(h, ffn_norm_w) -> bf16 split
    rmsnorm_split_k<DD, 256><<<NROWS, 256>>>(h, f_nw, hn_h, hn_l);

    // 8) fused interleaved w1/w3 GEMM with silu epilogue -> g (bf16 split)
    {
        const size_t wN8 = (size_t)I2P * DD / 8;
        conv_split_ilv8_k<<<(int)((wN8 + 255) / 256), 256>>>(w1_w, w3_w, w_h, w_l);
        dim3 grid(I2P / 128, NROWS / 128);
        gemm_bf16x3<<<grid, 256, GEMM_SMEM>>>(hn_h, hn_l, w_h, w_l, bffn, nullptr,
                                              I2P, DD, 0, 1, g_h, g_l, IKP);
    }

    // 9) f = g @ w2^T + b2  (K = IKP, weight K-padded)
    {
        const size_t wN8 = (size_t)DD * IKP / 8;
        conv_split8_k<<<(int)((wN8 + 255) / 256), 256>>>(w2_w, w_h, w_l,
                                                         DD, II, DD, IKP);
        dim3 grid(DD / 128, NROWS / 128);
        gemm_bf16x3<<<grid, 256, GEMM_SMEM>>>(g_h, g_l, w_h, w_l, w2_b, f,
                                              DD, IKP, DD, 0, nullptr, nullptr, 0);
    }

    // 10) out = h + rmsnorm(f, ffn_post_norm_w)
    rmsnorm_k<DD, 256><<<NROWS, 256>>>(f, fp_nw, h, out);
}